// round 8
// baseline (speedup 1.0000x reference)
#include <cuda_runtime.h>
#include <cuda_bf16.h>
#include <cstdint>

// Problem constants
#define B_SZ   2048
#define D_SZ   128
#define C_SZ   100000
#define KNN    10

// Fused kernel tiling
#define SPLITC 18
#define TILES  87
#define SLICE  (TILES * 64)        // 5568; 18*5568 = 100224 >= 100000
#define BM     128
#define BN     64
#define SSTRIDE 136                // bf16 elems per smem row (128 + 8 pad)
#define TILEBYTES (BN * SSTRIDE * 2)   // 17408
#define KHOIST 6                   // A k-steps hoisted in regs; 2 reloaded per tile

// Scratch (device globals; no allocation allowed)
__device__ __align__(16) float          g_enc_norm[B_SZ];
__device__ __align__(16) __nv_bfloat16  g_enc_bf16[B_SZ * D_SZ];
__device__ __align__(16) float          g_mem_norm[C_SZ];
__device__ __align__(16) __nv_bfloat16  g_mem_bf16[(size_t)C_SZ * D_SZ];
__device__ float g_partial[(size_t)B_SZ * SPLITC * 4 * KNN];  // 720 cand/row

// ---------------------------------------------------------------------------
// helpers
// ---------------------------------------------------------------------------
__device__ __forceinline__ uint32_t smem_u32(const void* p) {
    return (uint32_t)__cvta_generic_to_shared(p);
}

__device__ __forceinline__ void ldsm4(uint32_t& r0, uint32_t& r1, uint32_t& r2, uint32_t& r3,
                                      uint32_t addr) {
    asm volatile("ldmatrix.sync.aligned.m8n8.x4.shared.b16 {%0,%1,%2,%3}, [%4];\n"
                 : "=r"(r0), "=r"(r1), "=r"(r2), "=r"(r3) : "r"(addr));
}

__device__ __forceinline__ void mma16816(float* c, const uint32_t* a, const uint32_t* b) {
    asm volatile(
        "mma.sync.aligned.m16n8k16.row.col.f32.bf16.bf16.f32 "
        "{%0,%1,%2,%3},{%4,%5,%6,%7},{%8,%9},{%0,%1,%2,%3};\n"
        : "+f"(c[0]), "+f"(c[1]), "+f"(c[2]), "+f"(c[3])
        : "r"(a[0]), "r"(a[1]), "r"(a[2]), "r"(a[3]), "r"(b[0]), "r"(b[1]));
}

__device__ __forceinline__ void cp_async16(uint32_t saddr, const void* gptr, int srcbytes) {
    asm volatile("cp.async.cg.shared.global [%0], [%1], 16, %2;\n"
                 :: "r"(saddr), "l"(gptr), "r"(srcbytes));
}
__device__ __forceinline__ void cp_commit() { asm volatile("cp.async.commit_group;\n"); }
__device__ __forceinline__ void cp_wait1()  { asm volatile("cp.async.wait_group 1;\n"); }

__device__ __forceinline__ void topk_insert(float* best, float v) {
    if (v < best[KNN - 1]) {
        best[KNN - 1] = v;
        #pragma unroll
        for (int i = KNN - 1; i > 0; i--) {
            float lo = fminf(best[i - 1], best[i]);
            float hi = fmaxf(best[i - 1], best[i]);
            best[i - 1] = lo; best[i] = hi;
        }
    }
}

// ---------------------------------------------------------------------------
// Kernel A: encoder  enc = relu(state@W1+b1)@W2 + b2  (fp32), + bf16 copy + norms
// ---------------------------------------------------------------------------
__global__ void __launch_bounds__(128) enc_kernel(
    const float* __restrict__ state, const float* __restrict__ W1,
    const float* __restrict__ b1, const float* __restrict__ W2,
    const float* __restrict__ b2)
{
    __shared__ float s_buf[8][128];
    __shared__ float s_norm[8];
    const int t = threadIdx.x;
    const int row0 = blockIdx.x * 8;

    #pragma unroll
    for (int r = 0; r < 8; r++) s_buf[r][t] = state[(row0 + r) * D_SZ + t];
    if (t < 8) s_norm[t] = 0.f;
    __syncthreads();

    float acc[8];
    #pragma unroll
    for (int r = 0; r < 8; r++) acc[r] = 0.f;
    #pragma unroll 4
    for (int k = 0; k < D_SZ; k++) {
        float w = W1[k * D_SZ + t];
        #pragma unroll
        for (int r = 0; r < 8; r++) acc[r] = fmaf(s_buf[r][k], w, acc[r]);
    }
    __syncthreads();
    {
        float bb = b1[t];
        #pragma unroll
        for (int r = 0; r < 8; r++) s_buf[r][t] = fmaxf(acc[r] + bb, 0.f);
    }
    __syncthreads();

    float acc2[8];
    #pragma unroll
    for (int r = 0; r < 8; r++) acc2[r] = 0.f;
    #pragma unroll 4
    for (int k = 0; k < D_SZ; k++) {
        float w = W2[k * D_SZ + t];
        #pragma unroll
        for (int r = 0; r < 8; r++) acc2[r] = fmaf(s_buf[r][k], w, acc2[r]);
    }
    {
        float b2v = b2[t];
        #pragma unroll
        for (int r = 0; r < 8; r++) {
            float e = acc2[r] + b2v;
            g_enc_bf16[(row0 + r) * D_SZ + t] = __float2bfloat16(e);
            atomicAdd(&s_norm[r], e * e);
        }
    }
    __syncthreads();
    if (t < 8) g_enc_norm[row0 + t] = s_norm[t];
}

// ---------------------------------------------------------------------------
// Kernel B: memory -> bf16 + row norms (half range per launch)
// ---------------------------------------------------------------------------
__global__ void __launch_bounds__(128) prep_mem_kernel(const float* __restrict__ mem, int base)
{
    const int warp = threadIdx.x >> 5, lane = threadIdx.x & 31;
    const int row = base + blockIdx.x * 4 + warp;
    if (row >= C_SZ) return;
    const float4 v = ((const float4*)(mem + (size_t)row * D_SZ))[lane];
    float nrm = v.x * v.x + v.y * v.y + v.z * v.z + v.w * v.w;
    __nv_bfloat162 p0 = __floats2bfloat162_rn(v.x, v.y);
    __nv_bfloat162 p1 = __floats2bfloat162_rn(v.z, v.w);
    __nv_bfloat162* dst = (__nv_bfloat162*)(g_mem_bf16 + (size_t)row * D_SZ + lane * 4);
    dst[0] = p0; dst[1] = p1;
    #pragma unroll
    for (int o = 16; o; o >>= 1) nrm += __shfl_xor_sync(0xffffffffu, nrm, o);
    if (lane == 0) g_mem_norm[row] = nrm;
}

// ---------------------------------------------------------------------------
// Kernel C: fused bf16 GEMM + squared-distance screening + register top-10
// grid (SPLITC, 16) = 288 CTAs (2/SM), block 256.
// Warp tile 32x32 (4m x 2n warps) -> B-fragment reuse doubled, smem LDSM
// traffic nearly halved.  A: 6 of 8 k-steps hoisted, 2 reloaded per tile.
// Row-ownership after MMA fixed by shfl.xor(2) exchange (2 topk lists/thread).
// Triple-buffered cp.async B tiles.
// ---------------------------------------------------------------------------
__global__ void __launch_bounds__(256, 2) knn_kernel()
{
    extern __shared__ char smem[];
    __nv_bfloat16* s_enc = (__nv_bfloat16*)smem;                   // 34816 B
    char*          s_mem = smem + BM * SSTRIDE * 2;                // 3 x 17408 B
    __shared__ float s_enorm[BM];
    __shared__ float s_mnorm[3][BN];

    const int tid  = threadIdx.x;
    const int bx   = blockIdx.x;          // C slice
    const int by   = blockIdx.y;          // batch tile
    const int row0 = by * BM;
    const int cbase = bx * SLICE;

    // ---- persistent enc tile + norms
    for (int idx = tid; idx < BM * 16; idx += 256) {
        int r = idx >> 4, c8 = idx & 15;
        ((uint4*)(s_enc + r * SSTRIDE))[c8] =
            ((const uint4*)(g_enc_bf16 + (size_t)(row0 + r) * D_SZ))[c8];
    }
    if (tid < BM) s_enorm[tid] = g_enc_norm[row0 + tid];

    const uint32_t encBase = smem_u32(s_enc);
    const uint32_t memBase = smem_u32(s_mem);

    // ---- preload tiles 0 and 1 (two cp.async groups)
    #pragma unroll
    for (int pt = 0; pt < 2; pt++) {
        const uint32_t buf = memBase + pt * TILEBYTES;
        #pragma unroll
        for (int i = 0; i < 4; i++) {
            int idx = i * 256 + tid;
            int r = idx >> 4, c8 = idx & 15;
            int c = cbase + pt * BN + r;
            int cc = (c < C_SZ) ? c : 0;
            cp_async16(buf + (r * SSTRIDE + c8 * 8) * 2,
                       g_mem_bf16 + (size_t)cc * D_SZ + c8 * 8,
                       (c < C_SZ) ? 16 : 0);
        }
        if (tid < BN) {
            int c = cbase + pt * BN + tid;
            s_mnorm[pt][tid] = (c < C_SZ) ? g_mem_norm[c] : 3.0e37f;
        }
        cp_commit();
    }
    __syncthreads();    // enc tile visible

    const int warp = tid >> 5, lane = tid & 31;
    const int wm = warp & 3, wn = warp >> 2;         // warp tile: 32 rows x 32 cols
    const int lr = lane & 15, lc8 = lane >> 4;
    const int g  = lane >> 2, tq = lane & 3;
    const bool keep_lo = (tq < 2);                   // keep m-tile 0 rows after exchange

    // ---- hoist A fragments for k-steps [0, KHOIST): 6 x 2 x 4 = 48 regs
    uint32_t afrag[KHOIST][2][4];
    #pragma unroll
    for (int ks = 0; ks < KHOIST; ks++) {
        #pragma unroll
        for (int mi = 0; mi < 2; mi++) {
            uint32_t addr = encBase +
                ((wm * 32 + mi * 16 + lr) * SSTRIDE + ks * 16 + lc8 * 8) * 2;
            ldsm4(afrag[ks][mi][0], afrag[ks][mi][1], afrag[ks][mi][2], afrag[ks][mi][3], addr);
        }
    }

    float best0[KNN], best1[KNN];
    #pragma unroll
    for (int i = 0; i < KNN; i++) { best0[i] = 3.0e37f; best1[i] = 3.0e37f; }

    int cur = 0, nxt = 2;       // buffer indices mod 3
    for (int t = 0; t < TILES; t++) {
        cp_wait1();               // copy(t) complete
        __syncthreads();

        // ---- issue tile t+2 copy into buf nxt
        if (t + 2 < TILES) {
            const int c0n = cbase + (t + 2) * BN;
            const uint32_t nbuf = memBase + nxt * TILEBYTES;
            #pragma unroll
            for (int i = 0; i < 4; i++) {
                int idx = i * 256 + tid;
                int r = idx >> 4, c8 = idx & 15;
                int c = c0n + r;
                int cc = (c < C_SZ) ? c : 0;
                cp_async16(nbuf + (r * SSTRIDE + c8 * 8) * 2,
                           g_mem_bf16 + (size_t)cc * D_SZ + c8 * 8,
                           (c < C_SZ) ? 16 : 0);
            }
            if (tid < BN) {
                int c = c0n + tid;
                s_mnorm[nxt][tid] = (c < C_SZ) ? g_mem_norm[c] : 3.0e37f;
            }
        }
        cp_commit();

        // ---- MMA: 32 rows x 32 cols per warp
        float acc[2][4][4];
        #pragma unroll
        for (int mi = 0; mi < 2; mi++)
            #pragma unroll
            for (int ni = 0; ni < 4; ni++)
                #pragma unroll
                for (int q = 0; q < 4; q++) acc[mi][ni][q] = 0.f;

        const uint32_t curBase = memBase + cur * TILEBYTES;

        // k-steps KHOIST..7 first: transient A reload (short reg lifetime)
        #pragma unroll
        for (int ks = KHOIST; ks < 8; ks++) {
            uint32_t at[2][4];
            #pragma unroll
            for (int mi = 0; mi < 2; mi++) {
                uint32_t addr = encBase +
                    ((wm * 32 + mi * 16 + lr) * SSTRIDE + ks * 16 + lc8 * 8) * 2;
                ldsm4(at[mi][0], at[mi][1], at[mi][2], at[mi][3], addr);
            }
            #pragma unroll
            for (int nb = 0; nb < 2; nb++) {
                uint32_t q0, q1, q2, q3;
                ldsm4(q0, q1, q2, q3,
                      curBase + ((wn * 32 + nb * 16 + lr) * SSTRIDE + ks * 16 + lc8 * 8) * 2);
                uint32_t be[2] = {q0, q2};
                uint32_t bo[2] = {q1, q3};
                mma16816(acc[0][nb * 2 + 0], at[0], be);
                mma16816(acc[0][nb * 2 + 1], at[0], bo);
                mma16816(acc[1][nb * 2 + 0], at[1], be);
                mma16816(acc[1][nb * 2 + 1], at[1], bo);
            }
        }
        // hoisted k-steps
        #pragma unroll
        for (int ks = 0; ks < KHOIST; ks++) {
            #pragma unroll
            for (int nb = 0; nb < 2; nb++) {
                uint32_t q0, q1, q2, q3;
                ldsm4(q0, q1, q2, q3,
                      curBase + ((wn * 32 + nb * 16 + lr) * SSTRIDE + ks * 16 + lc8 * 8) * 2);
                uint32_t be[2] = {q0, q2};
                uint32_t bo[2] = {q1, q3};
                mma16816(acc[0][nb * 2 + 0], afrag[ks][0], be);
                mma16816(acc[0][nb * 2 + 1], afrag[ks][0], bo);
                mma16816(acc[1][nb * 2 + 0], afrag[ks][1], be);
                mma16816(acc[1][nb * 2 + 1], afrag[ks][1], bo);
            }
        }

        // ---- epilogue: exchange m-tile halves (shfl xor 2), screen, insert
        const float2* mn2 = (const float2*)s_mnorm[cur];
        #pragma unroll
        for (int ni = 0; ni < 4; ni++) {
            // my cols (pair) and partner cols (pair) norms
            const float2 mpK = mn2[wn * 16 + ni * 4 + tq];
            const float2 mpR = mn2[wn * 16 + ni * 4 + (tq ^ 2)];
            // send other m-tile's raw dots, receive partner's (for my kept rows)
            float o0 = keep_lo ? acc[1][ni][0] : acc[0][ni][0];
            float o1 = keep_lo ? acc[1][ni][1] : acc[0][ni][1];
            float o2 = keep_lo ? acc[1][ni][2] : acc[0][ni][2];
            float o3 = keep_lo ? acc[1][ni][3] : acc[0][ni][3];
            float i0 = __shfl_xor_sync(0xffffffffu, o0, 2);
            float i1 = __shfl_xor_sync(0xffffffffu, o1, 2);
            float i2 = __shfl_xor_sync(0xffffffffu, o2, 2);
            float i3 = __shfl_xor_sync(0xffffffffu, o3, 2);
            float k0 = keep_lo ? acc[0][ni][0] : acc[1][ni][0];
            float k1 = keep_lo ? acc[0][ni][1] : acc[1][ni][1];
            float k2 = keep_lo ? acc[0][ni][2] : acc[1][ni][2];
            float k3 = keep_lo ? acc[0][ni][3] : acc[1][ni][3];
            {   // row g of kept m-tile
                float s0 = fmaf(-2.f, k0, mpK.x);
                float s1 = fmaf(-2.f, k1, mpK.y);
                float s2 = fmaf(-2.f, i0, mpR.x);
                float s3 = fmaf(-2.f, i1, mpR.y);
                float mm = fminf(fminf(s0, s1), fminf(s2, s3));
                if (mm < best0[KNN - 1]) {
                    topk_insert(best0, s0); topk_insert(best0, s1);
                    topk_insert(best0, s2); topk_insert(best0, s3);
                }
            }
            {   // row g+8 of kept m-tile
                float u0 = fmaf(-2.f, k2, mpK.x);
                float u1 = fmaf(-2.f, k3, mpK.y);
                float u2 = fmaf(-2.f, i2, mpR.x);
                float u3 = fmaf(-2.f, i3, mpR.y);
                float um = fminf(fminf(u0, u1), fminf(u2, u3));
                if (um < best1[KNN - 1]) {
                    topk_insert(best1, u0); topk_insert(best1, u1);
                    topk_insert(best1, u2); topk_insert(best1, u3);
                }
            }
        }

        cur = (cur == 2) ? 0 : cur + 1;
        nxt = (nxt == 2) ? 0 : nxt + 1;
    }

    // ---- write partial top-10 (squared dist = enorm + screened)
    const int r0 = wm * 32 + (keep_lo ? 0 : 16) + g;
    const int lid4 = wn * 2 + (tq & 1);
    const float e0 = s_enorm[r0], e1 = s_enorm[r0 + 8];
    float* dst0 = g_partial + ((size_t)((row0 + r0) * SPLITC + bx) * 4 + lid4) * KNN;
    float* dst1 = g_partial + ((size_t)((row0 + r0 + 8) * SPLITC + bx) * 4 + lid4) * KNN;
    #pragma unroll
    for (int i = 0; i < KNN; i++) {
        dst0[i] = e0 + best0[i];
        dst1[i] = e1 + best1[i];
    }
}

// ---------------------------------------------------------------------------
// Kernel D: merge 720 squared-dist candidates/row -> mean of 10 smallest sqrt.
// Per-lane streaming top-10 then warp extract-min x10.  1 warp per row.
// ---------------------------------------------------------------------------
__global__ void __launch_bounds__(256) merge_kernel(float* __restrict__ out)
{
    const int warp = threadIdx.x >> 5, lane = threadIdx.x & 31;
    const int row = blockIdx.x * 8 + warp;
    const int NC = SPLITC * 4 * KNN;                  // 720
    const float* src = g_partial + (size_t)row * NC;

    float best[KNN];
    #pragma unroll
    for (int i = 0; i < KNN; i++) best[i] = 3.0e37f;
    for (int idx = lane; idx < NC; idx += 32)
        topk_insert(best, src[idx]);

    float sum = 0.f;
    for (int it = 0; it < KNN; it++) {
        float gm = best[0];
        #pragma unroll
        for (int o = 16; o; o >>= 1) gm = fminf(gm, __shfl_xor_sync(0xffffffffu, gm, o));
        sum += sqrtf(fmaxf(gm, 1e-12f));
        unsigned mask = __ballot_sync(0xffffffffu, best[0] == gm);
        int leader = __ffs(mask) - 1;
        if (lane == leader) {
            #pragma unroll
            for (int i = 0; i < KNN - 1; i++) best[i] = best[i + 1];
            best[KNN - 1] = 3.0e37f;
        }
    }
    if (lane == 0) out[row] = sum * (1.0f / KNN);
}

// ---------------------------------------------------------------------------
// launch: enc(0) prepA(1) prepB(2) knn(3) merge(4)  -- ncu window lands on knn
// ---------------------------------------------------------------------------
extern "C" void kernel_launch(void* const* d_in, const int* in_sizes, int n_in,
                              void* d_out, int out_size)
{
    (void)in_sizes; (void)n_in; (void)out_size;
    const float* state  = (const float*)d_in[0];
    const float* W1     = (const float*)d_in[1];
    const float* b1     = (const float*)d_in[2];
    const float* W2     = (const float*)d_in[3];
    const float* b2     = (const float*)d_in[4];
    const float* memory = (const float*)d_in[5];
    float* out = (float*)d_out;

    const int smemC = BM * SSTRIDE * 2 + 3 * TILEBYTES;   // 87040 bytes
    cudaFuncSetAttribute(knn_kernel, cudaFuncAttributeMaxDynamicSharedMemorySize, smemC);

    enc_kernel<<<B_SZ / 8, 128>>>(state, W1, b1, W2, b2);
    prep_mem_kernel<<<12500, 128>>>(memory, 0);
    prep_mem_kernel<<<12500, 128>>>(memory, 50000);
    knn_kernel<<<dim3(SPLITC, B_SZ / BM), 256, smemC>>>();
    merge_kernel<<<B_SZ / 8, 256>>>(out);
}